// round 12
// baseline (speedup 1.0000x reference)
#include <cuda_runtime.h>
#include <cstdint>

#define NROW     256
#define S_STEPS  4001
#define M_STEPS  4000
#define NCHUNK   148
#define CLEN     28
#define GP_SIZE  33152
#define CODE_UP   300
#define CODE_NONE 301
#define RINF     (1<<20)
#define NTHR     512

// ---- device scratch (zero-init at load; no allocations) ----
__device__ __align__(16) float g_Gp[GP_SIZE];   // packed G(i,c): row i at off=i*(i+3)/2, idx off+1+c
__device__ int   g_sum_r[NCHUNK * NROW];        // per-chunk transform: forced value (RINF = pass)
__device__ int   g_sum_K[NCHUNK];               // per-chunk transform: min-clamp
__device__ unsigned          g_count;           // barrier arrivals (self-resetting)
__device__ volatile unsigned g_gen;             // barrier generation (monotonic across replays)

__device__ __forceinline__ float xval(int i) {
    if (i >= 255) return 1.0f;
    if (i <= 0)   return 0.0f;
    return (float)i * (1.0f / 255.0f);
}

__device__ __forceinline__ float hnorm(const float* __restrict__ hd, int s) {
    return (s == 0) ? 1.0f : (hd[s - 1] + 1.0f) * 0.5f;
}

// classify step s: up (h>p), down (h<p, code=jmax), or none
__device__ __forceinline__ void make_step(const float* __restrict__ hd, int s,
                                          float& h, int& code) {
    h = hnorm(hd, s);
    int pi = (s == 0) ? (S_STEPS - 1) : (s - 1);
    float p = hnorm(hd, pi);
    if (h > p) {
        code = CODE_UP;
    } else if (h < p) {
        int jm = (int)(h * 255.0f);
        if (jm > 255) jm = 255;
        if (jm < 0)   jm = 0;
        while (jm < 255 && xval(jm + 1) <= h) ++jm;   // exact float semantics
        while (jm >= 0 && xval(jm) > h)      --jm;
        code = jm;                                    // jmax in [-1, 255]
    } else {
        code = CODE_NONE;
    }
}

// jax.nn.softplus = max(x,0) + log1p(exp(-|x|))
__device__ __forceinline__ float softplus_f(float x) {
    return fmaxf(x, 0.0f) + log1pf(expf(-fabsf(x)));
}

// transform compose: t_out = t2 ∘ t1 (t1 applied first)
__device__ __forceinline__ void comp(int r1, int K1, int r2, int K2, int& r, int& K) {
    r = (r2 != RINF) ? r2 : ((r1 != RINF) ? min(r1, K2) : RINF);
    K = min(K1, K2);
}

// software grid barrier — safe: 148 CTAs, 1/SM, all resident in one wave
__device__ __forceinline__ void grid_barrier() {
    __syncthreads();
    if (threadIdx.x == 0) {
        __threadfence();                       // release phase-A writes
        unsigned start = g_gen;                // read BEFORE arriving
        unsigned old = atomicAdd(&g_count, 1u);
        if (old == NCHUNK - 1) {
            g_count = 0;                       // reset for next graph replay
            __threadfence();
            atomicAdd((unsigned*)&g_gen, 1u);
        } else {
            while (g_gen == start) __nanosleep(32);   // backoff is load-bearing
        }
        __threadfence();                       // acquire
    }
    __syncthreads();
}

__global__ void __launch_bounds__(NTHR, 1)
kFused(const float* __restrict__ raw, const float* __restrict__ hd,
       float* __restrict__ out) {
    int k = blockIdx.x, tid = threadIdx.x;
    int half = tid >> 8;
    int t8   = tid & 255;
    int lnl  = t8 & 31;
    int wl   = t8 >> 5;
    int w    = tid >> 5;
    int ln   = tid & 31;

    __shared__ float sh[CLEN];
    __shared__ int   sc[CLEN];
    __shared__ float wtot[16];
    __shared__ float awt[8];                 // partial sums for 'a'
    __shared__ int   sR[NROW], sKm[NROW];    // upper half's compose transform
    __shared__ int   sC[NROW];               // combined entry state
    __shared__ float mat[CLEN * NROW];

    // ---- step descriptors for this block's chunk ----
    if (tid < CLEN) {
        int s = k * CLEN + tid;
        float h = 0.0f; int code = CODE_NONE;
        if (s < S_STEPS) make_step(hd, s, h, code);
        sh[tid] = h; sc[tid] = code;
    }

    // ---- phase A1: both G rows concurrently (one per 256-thread half),
    //      cross-warp prefix via direct wtot read (single sync) ----
    {
        int i = k + half * NCHUNK;
        bool valid = (i < NROW);
        float v = 0.0f;
        if (valid && t8 <= i) v = softplus_f(__ldg(raw + i * (i + 1) / 2 + t8));

        float s = v;
        #pragma unroll
        for (int o = 1; o < 32; o <<= 1) {
            float t = __shfl_up_sync(0xffffffffu, s, o);
            if (lnl >= o) s += t;
        }
        if (lnl == 31) wtot[half * 8 + wl] = s;
        __syncthreads();                        // wtot + sh/sc ready

        if (valid) {
            float pre = s, R = 0.0f;
            #pragma unroll
            for (int j = 0; j < 8; j++) {
                float t = wtot[half * 8 + j];
                if (j < wl) pre += t;
                R += t;
            }
            int off = i * (i + 3) / 2;
            if (t8 <= i) g_Gp[off + 1 + t8] = 2.0f * pre - R;
            if (t8 == 0) g_Gp[off] = -R;
        }
    }

    // ---- phase A2: chunk summary (lower half) ----
    if (half == 0) {
        float xi = xval(t8);
        int r = RINF, K = RINF;
        #pragma unroll
        for (int l = 0; l < CLEN; l++) {
            int cd = sc[l];
            if (cd == CODE_UP) {
                if (xi < sh[l]) r = t8;
            } else if (cd != CODE_NONE) {
                if (r != RINF) r = min(r, cd);
                K = min(K, cd);
            }
        }
        g_sum_r[k * NROW + t8] = r;
        if (t8 == 0) g_sum_K[k] = K;
    }

    // ---- grid barrier: all G rows + summaries visible ----
    grid_barrier();

    // ---- compose split (R9 form): lower [0,kmid), upper [kmid,k) ----
    {
        int kmid = k >> 1;
        int lo = half ? kmid : 0;
        int hi = half ? k : kmid;

        int R = RINF, Kc = RINF;
        const int* rr = g_sum_r + t8;
        int kk = lo;
        for (; kk + 8 <= hi; kk += 8) {
            int r0 = rr[(kk + 0) * NROW], r1 = rr[(kk + 1) * NROW];
            int r2 = rr[(kk + 2) * NROW], r3 = rr[(kk + 3) * NROW];
            int r4 = rr[(kk + 4) * NROW], r5 = rr[(kk + 5) * NROW];
            int r6 = rr[(kk + 6) * NROW], r7 = rr[(kk + 7) * NROW];
            int K0 = __ldg(g_sum_K + kk + 0), K1 = __ldg(g_sum_K + kk + 1);
            int K2 = __ldg(g_sum_K + kk + 2), K3 = __ldg(g_sum_K + kk + 3);
            int K4 = __ldg(g_sum_K + kk + 4), K5 = __ldg(g_sum_K + kk + 5);
            int K6 = __ldg(g_sum_K + kk + 6), K7 = __ldg(g_sum_K + kk + 7);
            int ra, Ka, rb, Kb, rc2, Kc2, rd, Kd, re, Ke, rf, Kf, rg, Kg;
            comp(r0, K0, r1, K1, ra, Ka);
            comp(r2, K2, r3, K3, rb, Kb);
            comp(r4, K4, r5, K5, rc2, Kc2);
            comp(r6, K6, r7, K7, rd, Kd);
            comp(ra, Ka, rb, Kb, re, Ke);
            comp(rc2, Kc2, rd, Kd, rf, Kf);
            comp(re, Ke, rf, Kf, rg, Kg);
            comp(R, Kc, rg, Kg, R, Kc);
        }
        for (; kk < hi; kk++) {
            comp(R, Kc, rr[kk * NROW], __ldg(g_sum_K + kk), R, Kc);
        }
        if (half == 1) { sR[t8] = R; sKm[t8] = Kc; }
        __syncthreads();
        if (half == 0) {
            int c = -1;
            c = (R != RINF) ? R : min(c, Kc);       // apply [0,kmid)
            int Rh = sR[t8], Kh = sKm[t8];
            c = (Rh != RINF) ? Rh : min(c, Kh);     // apply [kmid,k)
            sC[t8] = c;
        }
        __syncthreads();
    }

    // ---- phase C: ALU c-chain + load-minimized gather ----
    if (half == 0) {
        int i = t8;
        float xi = xval(i);
        int off = i * (i + 3) / 2;
        const float* __restrict__ rowp = g_Gp + off + 1;

        // R_i = -G(i,-1) = -g_Gp[off]; also the exact value of G(i,i)
        float g0 = __ldg(g_Gp + off);
        float Ri = -g0;
        float v = Ri;
        #pragma unroll
        for (int o = 16; o; o >>= 1) v += __shfl_xor_sync(0xffffffffu, v, o);
        if (lnl == 0) awt[wl] = v;

        int c = sC[i];
        float gi = __ldg(rowp + c);              // one unconditional entry load
        #pragma unroll
        for (int l = 0; l < CLEN; l++) {
            int cd = sc[l];
            if (cd == CODE_UP) {
                if (xi < sh[l]) { c = i; gi = Ri; }          // G(i,i)=R_i, no load
            } else if (cd != CODE_NONE) {
                if (cd < c) { c = cd; gi = __ldg(rowp + cd); } // load only on change
            }
            mat[l * NROW + i] = gi;
        }
    }
    __syncthreads();

    // ---- epilogue over 16 warps: warp w reduces steps l = w, w+16 ----
    float asum = 0.0f;
    #pragma unroll
    for (int j = 0; j < 8; j++) asum += awt[j];
    float ainv = 1.0f / asum;

    for (int l = w; l < CLEN; l += 16) {
        int s = k * CLEN + l;
        const float* row = mat + l * NROW;
        float t = 0.0f;
        #pragma unroll
        for (int j = 0; j < 8; j++) t += row[ln + 32 * j];
        #pragma unroll
        for (int o = 16; o; o >>= 1) t += __shfl_xor_sync(0xffffffffu, t, o);
        if (ln == 0 && s >= 1 && s < S_STEPS) out[s - 1] = t * ainv;
    }
}

extern "C" void kernel_launch(void* const* d_in, const int* in_sizes, int n_in,
                              void* d_out, int out_size) {
    const float* hd  = (const float*)d_in[0];
    const float* raw = (const float*)d_in[1];
    if (n_in >= 2 && in_sizes[0] != M_STEPS) {
        const float* t = hd; hd = raw; raw = t;
    }
    float* out = (float*)d_out;

    kFused<<<NCHUNK, NTHR>>>(raw, hd, out);
}

// round 14
// speedup vs baseline: 1.5779x; 1.5779x over previous
#include <cuda_runtime.h>
#include <cstdint>

#define NROW     256
#define S_STEPS  4001
#define M_STEPS  4000
#define NCHUNK   148
#define CLEN     28
#define CODE_UP   300
#define CODE_NONE 301
#define RINF     (1<<20)
#define NTHR     512

// ---- device scratch (zero-init at load; no allocations) ----
// Transposed G: g_GT[(c+1)*NROW + i] = G(i,c), c in [-1..i].
// Warp gathers at fixed step read lane-consecutive i -> coalesced on plateaus.
__device__ __align__(16) float g_GT[(NROW + 1) * NROW];
__device__ int   g_sum_r[NCHUNK * NROW];        // per-chunk transform: forced value (RINF = pass)
__device__ int   g_sum_K[NCHUNK];               // per-chunk transform: min-clamp
__device__ unsigned          g_count;           // barrier arrivals (self-resetting)
__device__ volatile unsigned g_gen;             // barrier generation (monotonic across replays)

__device__ __forceinline__ float xval(int i) {
    if (i >= 255) return 1.0f;
    if (i <= 0)   return 0.0f;
    return (float)i * (1.0f / 255.0f);
}

__device__ __forceinline__ float hnorm(const float* __restrict__ hd, int s) {
    return (s == 0) ? 1.0f : (hd[s - 1] + 1.0f) * 0.5f;
}

// classify step s: up (h>p), down (h<p, code=jmax), or none
__device__ __forceinline__ void make_step(const float* __restrict__ hd, int s,
                                          float& h, int& code) {
    h = hnorm(hd, s);
    int pi = (s == 0) ? (S_STEPS - 1) : (s - 1);
    float p = hnorm(hd, pi);
    if (h > p) {
        code = CODE_UP;
    } else if (h < p) {
        int jm = (int)(h * 255.0f);
        if (jm > 255) jm = 255;
        if (jm < 0)   jm = 0;
        while (jm < 255 && xval(jm + 1) <= h) ++jm;   // exact float semantics
        while (jm >= 0 && xval(jm) > h)      --jm;
        code = jm;                                    // jmax in [-1, 255]
    } else {
        code = CODE_NONE;
    }
}

// jax.nn.softplus = max(x,0) + log1p(exp(-|x|))
__device__ __forceinline__ float softplus_f(float x) {
    return fmaxf(x, 0.0f) + log1pf(expf(-fabsf(x)));
}

// transform compose: t_out = t2 ∘ t1 (t1 applied first)
__device__ __forceinline__ void comp(int r1, int K1, int r2, int K2, int& r, int& K) {
    r = (r2 != RINF) ? r2 : ((r1 != RINF) ? min(r1, K2) : RINF);
    K = min(K1, K2);
}

// software grid barrier — safe: 148 CTAs, 1/SM, all resident in one wave
__device__ __forceinline__ void grid_barrier() {
    __syncthreads();
    if (threadIdx.x == 0) {
        __threadfence();                       // release phase-A writes
        unsigned start = g_gen;                // read BEFORE arriving
        unsigned old = atomicAdd(&g_count, 1u);
        if (old == NCHUNK - 1) {
            g_count = 0;                       // reset for next graph replay
            __threadfence();
            atomicAdd((unsigned*)&g_gen, 1u);
        } else {
            while (g_gen == start) __nanosleep(32);   // backoff is load-bearing
        }
        __threadfence();                       // acquire
    }
    __syncthreads();
}

__global__ void __launch_bounds__(NTHR, 1)
kFused(const float* __restrict__ raw, const float* __restrict__ hd,
       float* __restrict__ out) {
    int k = blockIdx.x, tid = threadIdx.x;
    int half = tid >> 8;
    int t8   = tid & 255;
    int lnl  = t8 & 31;
    int wl   = t8 >> 5;
    int w    = tid >> 5;
    int ln   = tid & 31;

    __shared__ float sh[CLEN];
    __shared__ int   sc[CLEN];
    __shared__ float wtot[16];
    __shared__ float awt[8];                 // partial sums for 'a'
    __shared__ int   sR[NROW], sKm[NROW];    // upper half's compose transform
    __shared__ int   sC[NROW];               // combined entry state
    __shared__ float mat[CLEN * NROW];

    // ---- step descriptors for this block's chunk ----
    if (tid < CLEN) {
        int s = k * CLEN + tid;
        float h = 0.0f; int code = CODE_NONE;
        if (s < S_STEPS) make_step(hd, s, h, code);
        sh[tid] = h; sc[tid] = code;
    }

    // ---- phase A1: both G rows concurrently (one per 256-thread half) ----
    {
        int i = k + half * NCHUNK;
        bool valid = (i < NROW);
        float v = 0.0f;
        if (valid && t8 <= i) v = softplus_f(__ldg(raw + i * (i + 1) / 2 + t8));

        float s = v;
        #pragma unroll
        for (int o = 1; o < 32; o <<= 1) {
            float t = __shfl_up_sync(0xffffffffu, s, o);
            if (lnl >= o) s += t;
        }
        if (lnl == 31) wtot[half * 8 + wl] = s;
        __syncthreads();
        if (wl == 0) {
            float t = (lnl < 8) ? wtot[half * 8 + lnl] : 0.0f;
            #pragma unroll
            for (int o = 1; o < 8; o <<= 1) {
                float u = __shfl_up_sync(0xffffffffu, t, o);
                if (lnl >= o) t += u;
            }
            if (lnl < 8) wtot[half * 8 + lnl] = t;
        }
        __syncthreads();
        float pre = s + ((wl > 0) ? wtot[half * 8 + wl - 1] : 0.0f);
        float R = wtot[half * 8 + 7];

        if (valid) {
            // transposed store: G_T[(c+1)*NROW + i], c = t8
            if (t8 <= i) g_GT[(t8 + 1) * NROW + i] = 2.0f * pre - R;
            if (t8 == 0) g_GT[i] = -R;       // c = -1 plane (coalesced reads later)
        }
    }

    // ---- phase A2: chunk summary (lower half; sh/sc covered by A1 syncs) ----
    if (half == 0) {
        float xi = xval(t8);
        int r = RINF, K = RINF;
        #pragma unroll
        for (int l = 0; l < CLEN; l++) {
            int cd = sc[l];
            if (cd == CODE_UP) {
                if (xi < sh[l]) r = t8;
            } else if (cd != CODE_NONE) {
                if (r != RINF) r = min(r, cd);
                K = min(K, cd);
            }
        }
        g_sum_r[k * NROW + t8] = r;
        if (t8 == 0) g_sum_K[k] = K;
    }

    // ---- grid barrier: all G planes + summaries visible ----
    grid_barrier();

    // ---- compose split: lower composes [0,kmid), upper [kmid,k) ----
    {
        int kmid = k >> 1;
        int lo = half ? kmid : 0;
        int hi = half ? k : kmid;

        int R = RINF, Kc = RINF;
        const int* rr = g_sum_r + t8;
        int kk = lo;
        for (; kk + 8 <= hi; kk += 8) {
            int r0 = rr[(kk + 0) * NROW], r1 = rr[(kk + 1) * NROW];
            int r2 = rr[(kk + 2) * NROW], r3 = rr[(kk + 3) * NROW];
            int r4 = rr[(kk + 4) * NROW], r5 = rr[(kk + 5) * NROW];
            int r6 = rr[(kk + 6) * NROW], r7 = rr[(kk + 7) * NROW];
            int K0 = __ldg(g_sum_K + kk + 0), K1 = __ldg(g_sum_K + kk + 1);
            int K2 = __ldg(g_sum_K + kk + 2), K3 = __ldg(g_sum_K + kk + 3);
            int K4 = __ldg(g_sum_K + kk + 4), K5 = __ldg(g_sum_K + kk + 5);
            int K6 = __ldg(g_sum_K + kk + 6), K7 = __ldg(g_sum_K + kk + 7);
            int ra, Ka, rb, Kb, rc2, Kc2, rd, Kd, re, Ke, rf, Kf, rg, Kg;
            comp(r0, K0, r1, K1, ra, Ka);
            comp(r2, K2, r3, K3, rb, Kb);
            comp(r4, K4, r5, K5, rc2, Kc2);
            comp(r6, K6, r7, K7, rd, Kd);
            comp(ra, Ka, rb, Kb, re, Ke);
            comp(rc2, Kc2, rd, Kd, rf, Kf);
            comp(re, Ke, rf, Kf, rg, Kg);
            comp(R, Kc, rg, Kg, R, Kc);
        }
        for (; kk < hi; kk++) {
            comp(R, Kc, rr[kk * NROW], __ldg(g_sum_K + kk), R, Kc);
        }
        if (half == 1) { sR[t8] = R; sKm[t8] = Kc; }
        __syncthreads();
        if (half == 0) {
            int c = -1;
            c = (R != RINF) ? R : min(c, Kc);       // apply [0,kmid)
            int Rh = sR[t8], Kh = sKm[t8];
            c = (Rh != RINF) ? Rh : min(c, Kh);     // apply [kmid,k)
            sC[t8] = c;
        }
        __syncthreads();
    }

    // ---- phase C: ALU c-chain + UNCONDITIONAL transposed gather (coalesced
    //      on state plateaus; all 28 load addresses independent of loaded data) ----
    if (half == 0) {
        int i = t8;
        float xi = xval(i);

        // 'a' contribution: R_i = -G(i,-1) = -g_GT[i]  (fully coalesced)
        float v = -__ldg(g_GT + i);
        #pragma unroll
        for (int o = 16; o; o >>= 1) v += __shfl_xor_sync(0xffffffffu, v, o);
        if (lnl == 0) awt[wl] = v;

        int c = sC[i];
        float gv[CLEN];
        #pragma unroll
        for (int l = 0; l < CLEN; l++) {
            int cd = sc[l];
            if (cd == CODE_UP) {
                if (xi < sh[l]) c = i;
            } else if (cd != CODE_NONE) {
                c = min(c, cd);
            }
            gv[l] = __ldg(g_GT + (c + 1) * NROW + i);
        }
        #pragma unroll
        for (int l = 0; l < CLEN; l++) mat[l * NROW + i] = gv[l];
    }
    __syncthreads();

    // ---- epilogue over 16 warps: warp w reduces steps l = w, w+16 ----
    float asum = 0.0f;
    #pragma unroll
    for (int j = 0; j < 8; j++) asum += awt[j];
    float ainv = 1.0f / asum;

    for (int l = w; l < CLEN; l += 16) {
        int s = k * CLEN + l;
        const float* row = mat + l * NROW;
        float t = 0.0f;
        #pragma unroll
        for (int j = 0; j < 8; j++) t += row[ln + 32 * j];
        #pragma unroll
        for (int o = 16; o; o >>= 1) t += __shfl_xor_sync(0xffffffffu, t, o);
        if (ln == 0 && s >= 1 && s < S_STEPS) out[s - 1] = t * ainv;
    }
}

extern "C" void kernel_launch(void* const* d_in, const int* in_sizes, int n_in,
                              void* d_out, int out_size) {
    const float* hd  = (const float*)d_in[0];
    const float* raw = (const float*)d_in[1];
    if (n_in >= 2 && in_sizes[0] != M_STEPS) {
        const float* t = hd; hd = raw; raw = t;
    }
    float* out = (float*)d_out;

    kFused<<<NCHUNK, NTHR>>>(raw, hd, out);
}